// round 11
// baseline (speedup 1.0000x reference)
#include <cuda_runtime.h>
#include <math.h>

#define NN 100000
#define EE 1600000

// ---------------- scratch (static device globals; no allocation) ----------------
__device__ int   g_is64;
__device__ int   g_src[EE];
__device__ int   g_dst[EE];
__device__ int   g_cnt[NN];
__device__ int   g_rowptr[NN + 1];
__device__ int   g_fill[NN];
__device__ int   g_colidx[EE];
__device__ int   g_bsum[128];
__device__ int   g_boff[128];
__device__ float g_dinv[NN];
__device__ float g_y[(size_t)NN * 128];
__device__ float g_hA[(size_t)NN * 128];
__device__ float g_hB[(size_t)NN * 128];

// ---------------- edge-index format detection ----------------
// int64 little-endian with values < 2^31 -> all odd 32-bit words of the first
// 256 pairs are zero; int32 data makes them random node ids.
__global__ void k_detect(const int* __restrict__ u) {
    __shared__ int any;
    if (threadIdx.x == 0) any = 0;
    __syncthreads();
    if (u[2 * threadIdx.x + 1] != 0) atomicOr(&any, 1);
    __syncthreads();
    if (threadIdx.x == 0) g_is64 = any ? 0 : 1;
}

// ---------------- convert + degree histogram (fused) ----------------
__global__ void k_convert_hist(const int* __restrict__ u) {
    int i = blockIdx.x * blockDim.x + threadIdx.x;
    if (i >= EE) return;
    int s, d;
    if (g_is64) { s = u[2 * i]; d = u[2 * EE + 2 * i]; }
    else        { s = u[i];     d = u[EE + i]; }
    g_src[i] = s;
    g_dst[i] = d;
    atomicAdd(&g_cnt[d], 1);
}

__device__ __forceinline__ int block_scan_incl(int v) {
    __shared__ int ws[32];
    int lane = threadIdx.x & 31;
    int w = threadIdx.x >> 5;
#pragma unroll
    for (int o = 1; o < 32; o <<= 1) {
        int n = __shfl_up_sync(0xffffffffu, v, o);
        if (lane >= o) v += n;
    }
    if (lane == 31) ws[w] = v;
    __syncthreads();
    if (w == 0) {
        int s = ws[lane];
#pragma unroll
        for (int o = 1; o < 32; o <<= 1) {
            int n = __shfl_up_sync(0xffffffffu, s, o);
            if (lane >= o) s += n;
        }
        ws[lane] = s;
    }
    __syncthreads();
    if (w > 0) v += ws[w - 1];
    return v;
}

__global__ void k_scan_a() {  // 1024 threads/block; also produces g_dinv (fused)
    int i = blockIdx.x * 1024 + threadIdx.x;
    int c = (i < NN) ? g_cnt[i] : 0;
    if (i < NN) g_dinv[i] = rsqrtf((float)c + 1.0f);
    int s = block_scan_incl(c);
    if (i < NN) g_rowptr[i + 1] = s;
    if (threadIdx.x == 1023) g_bsum[blockIdx.x] = s;
}

__global__ void k_scan_b(int nblk) {  // 1 block, 1024 threads
    int v = (threadIdx.x < nblk) ? g_bsum[threadIdx.x] : 0;
    int s = block_scan_incl(v);
    if (threadIdx.x < nblk) g_boff[threadIdx.x] = s - v;  // exclusive
}

__global__ void k_scan_c() {  // also produces g_fill (fused fill_init)
    int i = blockIdx.x * 1024 + threadIdx.x;
    if (i < NN) {
        int v = g_rowptr[i + 1] + g_boff[blockIdx.x];
        g_rowptr[i + 1] = v;
        if (i + 1 < NN) g_fill[i + 1] = v;
        if (i == 0) { g_rowptr[0] = 0; g_fill[0] = 0; }
    }
}

__global__ void k_scatter() {
    int i = blockIdx.x * blockDim.x + threadIdx.x;
    if (i < EE) {
        int d = g_dst[i];
        int p = atomicAdd(&g_fill[d], 1);
        g_colidx[p] = g_src[i];
    }
}

// ---------------- GEMM: Y[n][j] = dinv[n] * sum_k H[n][k] W[k][j] ----------------
template <int FIN, int FOUT>
__global__ void __launch_bounds__(128) k_gemm(const float* __restrict__ H,
                                              const float* __restrict__ W,
                                              float* __restrict__ Y) {
    constexpr int BN = 64, KB = 32, TN = FOUT / 16, TM = 8;
    __shared__ float Ws[FIN * FOUT];
    __shared__ float Xs[KB][BN + 4];
    int tid = threadIdx.x;
    for (int i = tid; i < FIN * FOUT; i += 128) Ws[i] = W[i];
    int nb = blockIdx.x * BN;
    float acc[TM][TN];
#pragma unroll
    for (int i = 0; i < TM; i++)
#pragma unroll
        for (int j = 0; j < TN; j++) acc[i][j] = 0.f;
    int tx = tid & 15, ty = tid >> 4;
    int n0 = ty * TM, j0 = tx * TN;
    for (int kb = 0; kb < FIN; kb += KB) {
        __syncthreads();
        for (int idx = tid; idx < KB * BN; idx += 128) {
            int n = idx >> 5, k = idx & 31;
            int gn = nb + n;
            Xs[k][n] = (gn < NN) ? H[(size_t)gn * FIN + kb + k] : 0.f;
        }
        __syncthreads();
#pragma unroll
        for (int k = 0; k < KB; k++) {
            float xv[TM];
            float4 xa = *(const float4*)&Xs[k][n0];
            float4 xb = *(const float4*)&Xs[k][n0 + 4];
            xv[0] = xa.x; xv[1] = xa.y; xv[2] = xa.z; xv[3] = xa.w;
            xv[4] = xb.x; xv[5] = xb.y; xv[6] = xb.z; xv[7] = xb.w;
            float wv[TN];
            const float* wr = &Ws[(kb + k) * FOUT + j0];
#pragma unroll
            for (int j = 0; j < TN; j += 4) {
                float4 w4 = *(const float4*)&wr[j];
                wv[j] = w4.x; wv[j + 1] = w4.y; wv[j + 2] = w4.z; wv[j + 3] = w4.w;
            }
#pragma unroll
            for (int i = 0; i < TM; i++)
#pragma unroll
                for (int j = 0; j < TN; j++) acc[i][j] = fmaf(xv[i], wv[j], acc[i][j]);
        }
    }
#pragma unroll
    for (int i = 0; i < TM; i++) {
        int gn = nb + n0 + i;
        if (gn < NN) {
            float dv = g_dinv[gn];
            float* yr = Y + (size_t)gn * FOUT + j0;
#pragma unroll
            for (int j = 0; j < TN; j += 4) {
                float4 o;
                o.x = acc[i][j] * dv; o.y = acc[i][j + 1] * dv;
                o.z = acc[i][j + 2] * dv; o.w = acc[i][j + 3] * dv;
                *(float4*)&yr[j] = o;
            }
        }
    }
}

// ---------------- GEMM2 with fused bias + LayerNorm + ELU epilogue ----------------
// h2[n][j] = elu(LN_j(z[n]@W2 + b2; g2, be2)),  FIN=64, FOUT=128.
// Row j-reduction = 4-step shfl_xor over the 16-lane tx group (a full row's 128
// outputs live on the 16 tx lanes of one half-warp).
__global__ void __launch_bounds__(128) k_gemm2ln(const float* __restrict__ H,
                                                 const float* __restrict__ W,
                                                 const float* __restrict__ bias,
                                                 const float* __restrict__ gam,
                                                 const float* __restrict__ bet,
                                                 float* __restrict__ O) {
    constexpr int FIN = 64, FOUT = 128, BN = 64, KB = 32, TN = 8, TM = 8;
    __shared__ float Ws[FIN * FOUT];
    __shared__ float Xs[KB][BN + 4];
    int tid = threadIdx.x;
    for (int i = tid; i < FIN * FOUT; i += 128) Ws[i] = W[i];
    int nb = blockIdx.x * BN;
    float acc[TM][TN];
#pragma unroll
    for (int i = 0; i < TM; i++)
#pragma unroll
        for (int j = 0; j < TN; j++) acc[i][j] = 0.f;
    int tx = tid & 15, ty = tid >> 4;
    int n0 = ty * TM, j0 = tx * TN;
    for (int kb = 0; kb < FIN; kb += KB) {
        __syncthreads();
        for (int idx = tid; idx < KB * BN; idx += 128) {
            int n = idx >> 5, k = idx & 31;
            int gn = nb + n;
            Xs[k][n] = (gn < NN) ? H[(size_t)gn * FIN + kb + k] : 0.f;
        }
        __syncthreads();
#pragma unroll
        for (int k = 0; k < KB; k++) {
            float xv[TM];
            float4 xa = *(const float4*)&Xs[k][n0];
            float4 xb = *(const float4*)&Xs[k][n0 + 4];
            xv[0] = xa.x; xv[1] = xa.y; xv[2] = xa.z; xv[3] = xa.w;
            xv[4] = xb.x; xv[5] = xb.y; xv[6] = xb.z; xv[7] = xb.w;
            float wv[TN];
            const float* wr = &Ws[(kb + k) * FOUT + j0];
#pragma unroll
            for (int j = 0; j < TN; j += 4) {
                float4 w4 = *(const float4*)&wr[j];
                wv[j] = w4.x; wv[j + 1] = w4.y; wv[j + 2] = w4.z; wv[j + 3] = w4.w;
            }
#pragma unroll
            for (int i = 0; i < TM; i++)
#pragma unroll
                for (int j = 0; j < TN; j++) acc[i][j] = fmaf(xv[i], wv[j], acc[i][j]);
        }
    }
    // epilogue: bias + LN + ELU
    float bj[TN], gj[TN], ej[TN];
    {
        float4 a = *(const float4*)&bias[j0], b = *(const float4*)&bias[j0 + 4];
        bj[0]=a.x; bj[1]=a.y; bj[2]=a.z; bj[3]=a.w; bj[4]=b.x; bj[5]=b.y; bj[6]=b.z; bj[7]=b.w;
        a = *(const float4*)&gam[j0]; b = *(const float4*)&gam[j0 + 4];
        gj[0]=a.x; gj[1]=a.y; gj[2]=a.z; gj[3]=a.w; gj[4]=b.x; gj[5]=b.y; gj[6]=b.z; gj[7]=b.w;
        a = *(const float4*)&bet[j0]; b = *(const float4*)&bet[j0 + 4];
        ej[0]=a.x; ej[1]=a.y; ej[2]=a.z; ej[3]=a.w; ej[4]=b.x; ej[5]=b.y; ej[6]=b.z; ej[7]=b.w;
    }
#pragma unroll
    for (int i = 0; i < TM; i++) {
        int gn = nb + n0 + i;
        float t[TN];
        float s = 0.f;
#pragma unroll
        for (int j = 0; j < TN; j++) { t[j] = acc[i][j] + bj[j]; s += t[j]; }
#pragma unroll
        for (int o = 8; o > 0; o >>= 1) s += __shfl_xor_sync(0xffffffffu, s, o);
        float mu = s * (1.0f / 128.0f);
        float v = 0.f;
#pragma unroll
        for (int j = 0; j < TN; j++) { float d = t[j] - mu; v += d * d; }
#pragma unroll
        for (int o = 8; o > 0; o >>= 1) v += __shfl_xor_sync(0xffffffffu, v, o);
        float rs = rsqrtf(v * (1.0f / 128.0f) + 1e-5f);
        if (gn < NN) {
            float ov[TN];
#pragma unroll
            for (int j = 0; j < TN; j++) {
                float z = (t[j] - mu) * rs * gj[j] + ej[j];
                ov[j] = (z > 0.f) ? z : expm1f(z);
            }
            float* orow = O + (size_t)gn * FOUT + j0;
            *(float4*)&orow[0] = make_float4(ov[0], ov[1], ov[2], ov[3]);
            *(float4*)&orow[4] = make_float4(ov[4], ov[5], ov[6], ov[7]);
        }
    }
}

// ---------------- aggregation + bias + LayerNorm + ELU (warp per node) ----------------
// SCOUT: output is additionally scaled by dinv[node] (pre-scale for layer-2 x-space agg).
template <int F, bool SCOUT>
__global__ void __launch_bounds__(256) k_agg(const float* __restrict__ Y,
                                             const float* __restrict__ bias,
                                             const float* __restrict__ gam,
                                             const float* __restrict__ bet,
                                             float* __restrict__ O) {
    constexpr int VPL = F / 32;
    int wid = threadIdx.x >> 5;
    int lane = threadIdx.x & 31;
    int node = blockIdx.x * 8 + wid;
    if (node >= NN) return;
    int fi = lane * VPL;
    const float* yself = Y + (size_t)node * F + fi;
    float acc[VPL];
    if constexpr (VPL == 2) {
        float2 t = *(const float2*)yself; acc[0] = t.x; acc[1] = t.y;
    } else {
        float4 t = *(const float4*)yself;
        acc[0] = t.x; acc[1] = t.y; acc[2] = t.z; acc[3] = t.w;
    }
    int e = g_rowptr[node];
    int end = g_rowptr[node + 1];
    for (; e + 4 <= end; e += 4) {
        int s0 = __ldg(&g_colidx[e]);
        int s1 = __ldg(&g_colidx[e + 1]);
        int s2 = __ldg(&g_colidx[e + 2]);
        int s3 = __ldg(&g_colidx[e + 3]);
        const float* r0 = Y + (size_t)s0 * F + fi;
        const float* r1 = Y + (size_t)s1 * F + fi;
        const float* r2 = Y + (size_t)s2 * F + fi;
        const float* r3 = Y + (size_t)s3 * F + fi;
        if constexpr (VPL == 2) {
            float2 a = *(const float2*)r0, b = *(const float2*)r1;
            float2 c = *(const float2*)r2, d = *(const float2*)r3;
            acc[0] += (a.x + b.x) + (c.x + d.x);
            acc[1] += (a.y + b.y) + (c.y + d.y);
        } else {
            float4 a = *(const float4*)r0, b = *(const float4*)r1;
            float4 c = *(const float4*)r2, d = *(const float4*)r3;
            acc[0] += (a.x + b.x) + (c.x + d.x);
            acc[1] += (a.y + b.y) + (c.y + d.y);
            acc[2] += (a.z + b.z) + (c.z + d.z);
            acc[3] += (a.w + b.w) + (c.w + d.w);
        }
    }
    for (; e < end; e++) {
        int s0 = __ldg(&g_colidx[e]);
        const float* r0 = Y + (size_t)s0 * F + fi;
        if constexpr (VPL == 2) {
            float2 a = *(const float2*)r0; acc[0] += a.x; acc[1] += a.y;
        } else {
            float4 a = *(const float4*)r0;
            acc[0] += a.x; acc[1] += a.y; acc[2] += a.z; acc[3] += a.w;
        }
    }
    float dv = g_dinv[node];
    float t[VPL];
    float s1 = 0.f;
#pragma unroll
    for (int v = 0; v < VPL; v++) { t[v] = acc[v] * dv + bias[fi + v]; s1 += t[v]; }
#pragma unroll
    for (int o = 16; o > 0; o >>= 1) s1 += __shfl_xor_sync(0xffffffffu, s1, o);
    float mu = s1 * (1.0f / F);
    float s2 = 0.f;
#pragma unroll
    for (int v = 0; v < VPL; v++) { float d = t[v] - mu; s2 += d * d; }
#pragma unroll
    for (int o = 16; o > 0; o >>= 1) s2 += __shfl_xor_sync(0xffffffffu, s2, o);
    float rs = rsqrtf(s2 * (1.0f / F) + 1e-5f);
    float ov[VPL];
#pragma unroll
    for (int v = 0; v < VPL; v++) {
        float z = (t[v] - mu) * rs * gam[fi + v] + bet[fi + v];
        z = (z > 0.f) ? z : expm1f(z);
        ov[v] = SCOUT ? z * dv : z;
    }
    float* orow = O + (size_t)node * F + fi;
    if constexpr (VPL == 2) {
        *(float2*)orow = make_float2(ov[0], ov[1]);
    } else {
        *(float4*)orow = make_float4(ov[0], ov[1], ov[2], ov[3]);
    }
}

// ---------------- gather-only x-space aggregation (layer 2), F=64 ----------------
// z[d] = dinv[d] * (sum_src hS[src] + hS[d])   (hS already carries dinv[src])
__global__ void __launch_bounds__(256) k_aggX(const float* __restrict__ HS,
                                              float* __restrict__ Z) {
    int wid = threadIdx.x >> 5;
    int lane = threadIdx.x & 31;
    int node = blockIdx.x * 8 + wid;
    if (node >= NN) return;
    int fi = lane * 2;
    const float* yself = HS + (size_t)node * 64 + fi;
    float2 t0 = *(const float2*)yself;
    float a0 = t0.x, a1 = t0.y;
    int e = g_rowptr[node];
    int end = g_rowptr[node + 1];
    for (; e + 4 <= end; e += 4) {
        int s0 = __ldg(&g_colidx[e]);
        int s1 = __ldg(&g_colidx[e + 1]);
        int s2 = __ldg(&g_colidx[e + 2]);
        int s3 = __ldg(&g_colidx[e + 3]);
        float2 a = *(const float2*)(HS + (size_t)s0 * 64 + fi);
        float2 b = *(const float2*)(HS + (size_t)s1 * 64 + fi);
        float2 c = *(const float2*)(HS + (size_t)s2 * 64 + fi);
        float2 d = *(const float2*)(HS + (size_t)s3 * 64 + fi);
        a0 += (a.x + b.x) + (c.x + d.x);
        a1 += (a.y + b.y) + (c.y + d.y);
    }
    for (; e < end; e++) {
        int s0 = __ldg(&g_colidx[e]);
        float2 a = *(const float2*)(HS + (size_t)s0 * 64 + fi);
        a0 += a.x; a1 += a.y;
    }
    float dv = g_dinv[node];
    *(float2*)(Z + (size_t)node * 64 + fi) = make_float2(a0 * dv, a1 * dv);
}

// ---------------- head: (h@lw1+lb1) -> LN -> ELU -> @lw2+lb2 ----------------
__global__ void __launch_bounds__(256) k_head(const float* __restrict__ H,
                                              const float* __restrict__ lw1,
                                              const float* __restrict__ lb1,
                                              const float* __restrict__ g4,
                                              const float* __restrict__ be4,
                                              const float* __restrict__ lw2,
                                              const float* __restrict__ lb2,
                                              float* __restrict__ out) {
    __shared__ float W1s[64 * 32];
    __shared__ float W2s[32 * 32];
    __shared__ float hs[8][64];
    int tid = threadIdx.x;
    for (int i = tid; i < 64 * 32; i += 256) W1s[i] = lw1[i];
    for (int i = tid; i < 32 * 32; i += 256) W2s[i] = lw2[i];
    int wid = tid >> 5, lane = tid & 31;
    int node = blockIdx.x * 8 + wid;
    __syncthreads();
    if (node >= NN) return;
    const float* hr = H + (size_t)node * 64;
    hs[wid][lane] = hr[lane];
    hs[wid][lane + 32] = hr[lane + 32];
    __syncwarp();
    float u = lb1[lane];
#pragma unroll
    for (int k = 0; k < 64; k++) u = fmaf(hs[wid][k], W1s[k * 32 + lane], u);
    float s = u;
#pragma unroll
    for (int o = 16; o > 0; o >>= 1) s += __shfl_xor_sync(0xffffffffu, s, o);
    float mu = s * (1.0f / 32.0f);
    float d = u - mu;
    float s2 = d * d;
#pragma unroll
    for (int o = 16; o > 0; o >>= 1) s2 += __shfl_xor_sync(0xffffffffu, s2, o);
    float rs = rsqrtf(s2 * (1.0f / 32.0f) + 1e-5f);
    float v = d * rs * g4[lane] + be4[lane];
    v = (v > 0.f) ? v : expm1f(v);
    float o2 = lb2[lane];
#pragma unroll
    for (int k = 0; k < 32; k++) {
        float vk = __shfl_sync(0xffffffffu, v, k);
        o2 = fmaf(vk, W2s[k * 32 + lane], o2);
    }
    out[(size_t)node * 32 + lane] = o2;
}

// ---------------- launch ----------------
extern "C" void kernel_launch(void* const* d_in, const int* in_sizes, int n_in,
                              void* d_out, int out_size) {
    const float* x   = (const float*)d_in[0];
    const int*   ei  = (const int*)d_in[1];
    const float* W1  = (const float*)d_in[2];
    const float* b1  = (const float*)d_in[3];
    const float* g1  = (const float*)d_in[4];
    const float* be1 = (const float*)d_in[5];
    const float* W2  = (const float*)d_in[6];
    const float* b2  = (const float*)d_in[7];
    const float* g2  = (const float*)d_in[8];
    const float* be2 = (const float*)d_in[9];
    const float* W3  = (const float*)d_in[10];
    const float* b3  = (const float*)d_in[11];
    const float* g3  = (const float*)d_in[12];
    const float* be3 = (const float*)d_in[13];
    const float* lw1 = (const float*)d_in[14];
    const float* lb1 = (const float*)d_in[15];
    const float* g4  = (const float*)d_in[16];
    const float* be4 = (const float*)d_in[17];
    const float* lw2 = (const float*)d_in[18];
    const float* lb2 = (const float*)d_in[19];
    float* out = (float*)d_out;

    void *py, *pA, *pB, *pc;
    cudaGetSymbolAddress(&py, g_y);
    cudaGetSymbolAddress(&pA, g_hA);
    cudaGetSymbolAddress(&pB, g_hB);
    cudaGetSymbolAddress(&pc, g_cnt);
    float* Y  = (float*)py;
    float* hA = (float*)pA;
    float* hB = (float*)pB;

    const int EB  = (EE + 255) / 256;
    const int NSC = (NN + 1023) / 1024;  // 98
    const int GB  = (NN + 63) / 64;
    const int AB  = (NN + 7) / 8;

    cudaMemsetAsync(pc, 0, NN * sizeof(int), 0);
    k_detect<<<1, 256>>>(ei);
    k_convert_hist<<<EB, 256>>>(ei);
    k_scan_a<<<NSC, 1024>>>();
    k_scan_b<<<1, 1024>>>(NSC);
    k_scan_c<<<NSC, 1024>>>();
    k_scatter<<<EB, 256>>>();

    // layer 1: transform -> aggregate (+LN+ELU, output pre-scaled by dinv)
    k_gemm<128, 64><<<GB, 128>>>(x, W1, Y);
    k_agg<64, true><<<AB, 256>>>(Y, b1, g1, be1, hA);   // hA = dinv * h1
    // layer 2: aggregate in x-space (64 wide) -> transform (+bias+LN+ELU fused)
    k_aggX<<<AB, 256>>>(hA, hB);                        // hB = z (64)
    k_gemm2ln<<<GB, 128>>>(hB, W2, b2, g2, be2, Y);     // Y = h2 (128)
    // layer 3: transform -> aggregate (+LN+ELU)
    k_gemm<128, 64><<<GB, 128>>>(Y, W3, hB);            // hB = dinv * (h2 W3)
    k_agg<64, false><<<AB, 256>>>(hB, b3, g3, be3, hA); // hA = h3
    k_head<<<AB, 256>>>(hA, lw1, lb1, g4, be4, lw2, lb2, out);
}

// round 13
// speedup vs baseline: 1.2988x; 1.2988x over previous
#include <cuda_runtime.h>
#include <math.h>

#define NN 100000
#define EE 1600000

typedef unsigned long long ull;

// ---------------- scratch (static device globals; no allocation) ----------------
__device__ int   g_is64;
__device__ int   g_src[EE];
__device__ int   g_dst[EE];
__device__ int   g_cnt[NN];
__device__ int   g_rowptr[NN + 1];
__device__ int   g_fill[NN];
__device__ int   g_colidx[EE];
__device__ int   g_bsum[128];
__device__ int   g_boff[128];
__device__ float g_dinv[NN];
__device__ float g_y[(size_t)NN * 128];
__device__ float g_hA[(size_t)NN * 128];
__device__ float g_hB[(size_t)NN * 128];

// ---------------- f32x2 helpers ----------------
__device__ __forceinline__ void ffma2(ull& d, ull a, ull b) {
    asm("fma.rn.f32x2 %0, %1, %2, %0;" : "+l"(d) : "l"(a), "l"(b));
}
__device__ __forceinline__ float sum2(ull v) {
    float lo, hi;
    asm("mov.b64 {%0, %1}, %2;" : "=f"(lo), "=f"(hi) : "l"(v));
    return lo + hi;
}

// ---------------- edge-index format detection + conversion ----------------
// int64 little-endian with values < 2^31 -> all odd 32-bit words of the first
// 256 pairs are zero; int32 data makes them random node ids.
__global__ void k_detect(const int* __restrict__ u) {
    __shared__ int any;
    if (threadIdx.x == 0) any = 0;
    __syncthreads();
    if (u[2 * threadIdx.x + 1] != 0) atomicOr(&any, 1);
    __syncthreads();
    if (threadIdx.x == 0) g_is64 = any ? 0 : 1;
}

__global__ void k_convert(const int* __restrict__ u) {
    int i = blockIdx.x * blockDim.x + threadIdx.x;
    if (i >= EE) return;
    if (g_is64) {
        g_src[i] = u[2 * i];
        g_dst[i] = u[2 * EE + 2 * i];
    } else {
        g_src[i] = u[i];
        g_dst[i] = u[EE + i];
    }
}

// ---------------- degree / CSR build ----------------
__global__ void k_hist() {
    int i = blockIdx.x * blockDim.x + threadIdx.x;
    if (i < EE) atomicAdd(&g_cnt[g_dst[i]], 1);
}

__device__ __forceinline__ int block_scan_incl(int v) {
    __shared__ int ws[32];
    int lane = threadIdx.x & 31;
    int w = threadIdx.x >> 5;
#pragma unroll
    for (int o = 1; o < 32; o <<= 1) {
        int n = __shfl_up_sync(0xffffffffu, v, o);
        if (lane >= o) v += n;
    }
    if (lane == 31) ws[w] = v;
    __syncthreads();
    if (w == 0) {
        int s = ws[lane];
#pragma unroll
        for (int o = 1; o < 32; o <<= 1) {
            int n = __shfl_up_sync(0xffffffffu, s, o);
            if (lane >= o) s += n;
        }
        ws[lane] = s;
    }
    __syncthreads();
    if (w > 0) v += ws[w - 1];
    return v;
}

__global__ void k_scan_a() {  // 1024 threads/block; also produces g_dinv (fused)
    int i = blockIdx.x * 1024 + threadIdx.x;
    int c = (i < NN) ? g_cnt[i] : 0;
    if (i < NN) g_dinv[i] = rsqrtf((float)c + 1.0f);
    int s = block_scan_incl(c);
    if (i < NN) g_rowptr[i + 1] = s;
    if (threadIdx.x == 1023) g_bsum[blockIdx.x] = s;
}

__global__ void k_scan_b(int nblk) {  // 1 block, 1024 threads
    int v = (threadIdx.x < nblk) ? g_bsum[threadIdx.x] : 0;
    int s = block_scan_incl(v);
    if (threadIdx.x < nblk) g_boff[threadIdx.x] = s - v;  // exclusive
}

__global__ void k_scan_c() {  // also produces g_fill (fused fill_init)
    int i = blockIdx.x * 1024 + threadIdx.x;
    if (i < NN) {
        int v = g_rowptr[i + 1] + g_boff[blockIdx.x];
        g_rowptr[i + 1] = v;
        if (i + 1 < NN) g_fill[i + 1] = v;
        if (i == 0) { g_rowptr[0] = 0; g_fill[0] = 0; }
    }
}

__global__ void k_scatter() {
    int i = blockIdx.x * blockDim.x + threadIdx.x;
    if (i < EE) {
        int d = g_dst[i];
        int p = atomicAdd(&g_fill[d], 1);
        g_colidx[p] = g_src[i];
    }
}

// ---------------- GEMM (f32x2): Y[n][j] = dinv[n] * sum_k H[n][k] W[k][j] ----------
// Accumulators are k-paired partial sums in packed f32x2 registers.
// Tile sized so acc2 occupies exactly 64 regs: FOUT=64 -> TM=8,BN=64;
// FOUT=128 -> TM=4,BN=32. 128 threads either way.
template <int FIN, int FOUT>
__global__ void __launch_bounds__(128) k_gemmx(const float* __restrict__ H,
                                               const float* __restrict__ W,
                                               float* __restrict__ Y) {
    constexpr int TN = FOUT / 16;                 // 4 or 8 (per-thread j count)
    constexpr int TM = (FOUT == 128) ? 4 : 8;     // per-thread rows
    constexpr int BN = TM * 8;                    // 8 ty groups of 16 tx lanes
    constexpr int KB = 32;
    __shared__ ull Wp[(FIN / 2) * FOUT];          // {W[2kk][j], W[2kk+1][j]}
    __shared__ ull Xs2[BN][KB / 2];               // {H[n][2kk], H[n][2kk+1]}
    int tid = threadIdx.x;

    for (int idx = tid; idx < (FIN / 2) * FOUT; idx += 128) {
        int kk = idx / FOUT, j = idx % FOUT;
        float2 p = make_float2(W[(2 * kk) * FOUT + j], W[(2 * kk + 1) * FOUT + j]);
        Wp[idx] = *(ull*)&p;
    }

    int nb = blockIdx.x * BN;
    ull acc2[TM][TN];
#pragma unroll
    for (int i = 0; i < TM; i++)
#pragma unroll
        for (int j = 0; j < TN; j++) acc2[i][j] = 0ull;

    int tx = tid & 15, ty = tid >> 4;
    int n0 = ty * TM, j0 = tx * TN;

    for (int kb = 0; kb < FIN; kb += KB) {
        __syncthreads();
        for (int idx = tid; idx < BN * (KB / 2); idx += 128) {
            int n = idx / (KB / 2), kk = idx % (KB / 2);
            int gn = nb + n;
            float2 p = (gn < NN) ? *(const float2*)&H[(size_t)gn * FIN + kb + 2 * kk]
                                 : make_float2(0.f, 0.f);
            Xs2[n][kk] = *(ull*)&p;
        }
        __syncthreads();
        int kb2 = (kb / 2) * FOUT;
#pragma unroll
        for (int kk = 0; kk < KB / 2; kk++) {
            ull x2[TM];
#pragma unroll
            for (int i = 0; i < TM; i++) x2[i] = Xs2[n0 + i][kk];
            ull w2[TN];
            const ull* wr = &Wp[kb2 + kk * FOUT + j0];
#pragma unroll
            for (int j = 0; j < TN; j++) w2[j] = wr[j];
#pragma unroll
            for (int i = 0; i < TM; i++)
#pragma unroll
                for (int j = 0; j < TN; j++) ffma2(acc2[i][j], x2[i], w2[j]);
        }
    }

#pragma unroll
    for (int i = 0; i < TM; i++) {
        int gn = nb + n0 + i;
        if (gn < NN) {
            float dv = g_dinv[gn];
            float* yr = Y + (size_t)gn * FOUT + j0;
#pragma unroll
            for (int j = 0; j < TN; j += 4) {
                float4 o;
                o.x = sum2(acc2[i][j + 0]) * dv;
                o.y = sum2(acc2[i][j + 1]) * dv;
                o.z = sum2(acc2[i][j + 2]) * dv;
                o.w = sum2(acc2[i][j + 3]) * dv;
                *(float4*)&yr[j] = o;
            }
        }
    }
}

// ---------------- aggregation + bias + LayerNorm + ELU (warp per node) ----------------
template <int F>
__global__ void __launch_bounds__(256) k_agg(const float* __restrict__ Y,
                                             const float* __restrict__ bias,
                                             const float* __restrict__ gam,
                                             const float* __restrict__ bet,
                                             float* __restrict__ O) {
    constexpr int VPL = F / 32;
    int wid = threadIdx.x >> 5;
    int lane = threadIdx.x & 31;
    int node = blockIdx.x * 8 + wid;
    if (node >= NN) return;
    int fi = lane * VPL;
    const float* yself = Y + (size_t)node * F + fi;
    float acc[VPL];
    if constexpr (VPL == 2) {
        float2 t = *(const float2*)yself; acc[0] = t.x; acc[1] = t.y;
    } else {
        float4 t = *(const float4*)yself;
        acc[0] = t.x; acc[1] = t.y; acc[2] = t.z; acc[3] = t.w;
    }
    int e = g_rowptr[node];
    int end = g_rowptr[node + 1];
    for (; e + 4 <= end; e += 4) {
        int s0 = __ldg(&g_colidx[e]);
        int s1 = __ldg(&g_colidx[e + 1]);
        int s2 = __ldg(&g_colidx[e + 2]);
        int s3 = __ldg(&g_colidx[e + 3]);
        const float* r0 = Y + (size_t)s0 * F + fi;
        const float* r1 = Y + (size_t)s1 * F + fi;
        const float* r2 = Y + (size_t)s2 * F + fi;
        const float* r3 = Y + (size_t)s3 * F + fi;
        if constexpr (VPL == 2) {
            float2 a = *(const float2*)r0, b = *(const float2*)r1;
            float2 c = *(const float2*)r2, d = *(const float2*)r3;
            acc[0] += (a.x + b.x) + (c.x + d.x);
            acc[1] += (a.y + b.y) + (c.y + d.y);
        } else {
            float4 a = *(const float4*)r0, b = *(const float4*)r1;
            float4 c = *(const float4*)r2, d = *(const float4*)r3;
            acc[0] += (a.x + b.x) + (c.x + d.x);
            acc[1] += (a.y + b.y) + (c.y + d.y);
            acc[2] += (a.z + b.z) + (c.z + d.z);
            acc[3] += (a.w + b.w) + (c.w + d.w);
        }
    }
    for (; e < end; e++) {
        int s0 = __ldg(&g_colidx[e]);
        const float* r0 = Y + (size_t)s0 * F + fi;
        if constexpr (VPL == 2) {
            float2 a = *(const float2*)r0; acc[0] += a.x; acc[1] += a.y;
        } else {
            float4 a = *(const float4*)r0;
            acc[0] += a.x; acc[1] += a.y; acc[2] += a.z; acc[3] += a.w;
        }
    }
    float dv = g_dinv[node];
    float t[VPL];
    float s1 = 0.f;
#pragma unroll
    for (int v = 0; v < VPL; v++) { t[v] = acc[v] * dv + bias[fi + v]; s1 += t[v]; }
#pragma unroll
    for (int o = 16; o > 0; o >>= 1) s1 += __shfl_xor_sync(0xffffffffu, s1, o);
    float mu = s1 * (1.0f / F);
    float s2 = 0.f;
#pragma unroll
    for (int v = 0; v < VPL; v++) { float d = t[v] - mu; s2 += d * d; }
#pragma unroll
    for (int o = 16; o > 0; o >>= 1) s2 += __shfl_xor_sync(0xffffffffu, s2, o);
    float rs = rsqrtf(s2 * (1.0f / F) + 1e-5f);
    float ov[VPL];
#pragma unroll
    for (int v = 0; v < VPL; v++) {
        float z = (t[v] - mu) * rs * gam[fi + v] + bet[fi + v];
        ov[v] = (z > 0.f) ? z : expm1f(z);
    }
    float* orow = O + (size_t)node * F + fi;
    if constexpr (VPL == 2) {
        *(float2*)orow = make_float2(ov[0], ov[1]);
    } else {
        *(float4*)orow = make_float4(ov[0], ov[1], ov[2], ov[3]);
    }
}

// ---------------- head: (h@lw1+lb1) -> LN -> ELU -> @lw2+lb2 ----------------
__global__ void __launch_bounds__(256) k_head(const float* __restrict__ H,
                                              const float* __restrict__ lw1,
                                              const float* __restrict__ lb1,
                                              const float* __restrict__ g4,
                                              const float* __restrict__ be4,
                                              const float* __restrict__ lw2,
                                              const float* __restrict__ lb2,
                                              float* __restrict__ out) {
    __shared__ float W1s[64 * 32];
    __shared__ float W2s[32 * 32];
    __shared__ float hs[8][64];
    int tid = threadIdx.x;
    for (int i = tid; i < 64 * 32; i += 256) W1s[i] = lw1[i];
    for (int i = tid; i < 32 * 32; i += 256) W2s[i] = lw2[i];
    int wid = tid >> 5, lane = tid & 31;
    int node = blockIdx.x * 8 + wid;
    __syncthreads();
    if (node >= NN) return;
    const float* hr = H + (size_t)node * 64;
    hs[wid][lane] = hr[lane];
    hs[wid][lane + 32] = hr[lane + 32];
    __syncwarp();
    float u = lb1[lane];
#pragma unroll
    for (int k = 0; k < 64; k++) u = fmaf(hs[wid][k], W1s[k * 32 + lane], u);
    float s = u;
#pragma unroll
    for (int o = 16; o > 0; o >>= 1) s += __shfl_xor_sync(0xffffffffu, s, o);
    float mu = s * (1.0f / 32.0f);
    float d = u - mu;
    float s2 = d * d;
#pragma unroll
    for (int o = 16; o > 0; o >>= 1) s2 += __shfl_xor_sync(0xffffffffu, s2, o);
    float rs = rsqrtf(s2 * (1.0f / 32.0f) + 1e-5f);
    float v = d * rs * g4[lane] + be4[lane];
    v = (v > 0.f) ? v : expm1f(v);
    float o2 = lb2[lane];
#pragma unroll
    for (int k = 0; k < 32; k++) {
        float vk = __shfl_sync(0xffffffffu, v, k);
        o2 = fmaf(vk, W2s[k * 32 + lane], o2);
    }
    out[(size_t)node * 32 + lane] = o2;
}

// ---------------- launch ----------------
extern "C" void kernel_launch(void* const* d_in, const int* in_sizes, int n_in,
                              void* d_out, int out_size) {
    const float* x   = (const float*)d_in[0];
    const int*   ei  = (const int*)d_in[1];
    const float* W1  = (const float*)d_in[2];
    const float* b1  = (const float*)d_in[3];
    const float* g1  = (const float*)d_in[4];
    const float* be1 = (const float*)d_in[5];
    const float* W2  = (const float*)d_in[6];
    const float* b2  = (const float*)d_in[7];
    const float* g2  = (const float*)d_in[8];
    const float* be2 = (const float*)d_in[9];
    const float* W3  = (const float*)d_in[10];
    const float* b3  = (const float*)d_in[11];
    const float* g3  = (const float*)d_in[12];
    const float* be3 = (const float*)d_in[13];
    const float* lw1 = (const float*)d_in[14];
    const float* lb1 = (const float*)d_in[15];
    const float* g4  = (const float*)d_in[16];
    const float* be4 = (const float*)d_in[17];
    const float* lw2 = (const float*)d_in[18];
    const float* lb2 = (const float*)d_in[19];
    float* out = (float*)d_out;

    void *py, *pA, *pB, *pc;
    cudaGetSymbolAddress(&py, g_y);
    cudaGetSymbolAddress(&pA, g_hA);
    cudaGetSymbolAddress(&pB, g_hB);
    cudaGetSymbolAddress(&pc, g_cnt);
    float* Y  = (float*)py;
    float* hA = (float*)pA;
    float* hB = (float*)pB;

    const int EB   = (EE + 255) / 256;
    const int NSC  = (NN + 1023) / 1024;  // 98
    const int GB64 = (NN + 63) / 64;      // gemm blocks, FOUT=64 (BN=64)
    const int GB32 = (NN + 31) / 32;      // gemm blocks, FOUT=128 (BN=32)
    const int AB   = (NN + 7) / 8;

    cudaMemsetAsync(pc, 0, NN * sizeof(int), 0);
    k_detect<<<1, 256>>>(ei);
    k_convert<<<EB, 256>>>(ei);
    k_hist<<<EB, 256>>>();
    k_scan_a<<<NSC, 1024>>>();
    k_scan_b<<<1, 1024>>>(NSC);
    k_scan_c<<<NSC, 1024>>>();
    k_scatter<<<EB, 256>>>();

    k_gemmx<128, 64><<<GB64, 128>>>(x, W1, Y);
    k_agg<64><<<AB, 256>>>(Y, b1, g1, be1, hA);
    k_gemmx<64, 128><<<GB32, 128>>>(hA, W2, Y);
    k_agg<128><<<AB, 256>>>(Y, b2, g2, be2, hB);
    k_gemmx<128, 64><<<GB64, 128>>>(hB, W3, Y);
    k_agg<64><<<AB, 256>>>(Y, b3, g3, be3, hA);
    k_head<<<AB, 256>>>(hA, lw1, lb1, g4, be4, lw2, lb2, out);
}

// round 15
// speedup vs baseline: 1.4249x; 1.0971x over previous
#include <cuda_runtime.h>
#include <math.h>

#define NN 100000
#define EE 1600000

// ---------------- scratch (static device globals; no allocation) ----------------
__device__ int   g_is64;
__device__ int   g_cnt[NN];
__device__ int   g_rowptr[NN + 1];
__device__ int   g_fill[NN];
__device__ int   g_colidx[EE];
__device__ int   g_bsum[128];
__device__ int   g_boff[128];
__device__ float g_dinv[NN];
__device__ float g_y[(size_t)NN * 128];
__device__ float g_hA[(size_t)NN * 128];
__device__ float g_hB[(size_t)NN * 128];

// ---------------- edge-index format detection ----------------
// int64 little-endian with values < 2^31 -> all odd 32-bit words of the first
// 256 pairs are zero; int32 data makes them random node ids.
__global__ void k_detect(const int* __restrict__ u) {
    __shared__ int any;
    if (threadIdx.x == 0) any = 0;
    __syncthreads();
    if (u[2 * threadIdx.x + 1] != 0) atomicOr(&any, 1);
    __syncthreads();
    if (threadIdx.x == 0) g_is64 = any ? 0 : 1;
}

// ---------------- degree / CSR build (direct edge reads) ----------------
__global__ void k_hist(const int* __restrict__ u) {
    int i = blockIdx.x * blockDim.x + threadIdx.x;
    if (i >= EE) return;
    int d = g_is64 ? u[2 * EE + 2 * i] : u[EE + i];
    atomicAdd(&g_cnt[d], 1);
}

__global__ void k_dinv() {
    int i = blockIdx.x * blockDim.x + threadIdx.x;
    if (i < NN) g_dinv[i] = rsqrtf((float)g_cnt[i] + 1.0f);
}

__device__ __forceinline__ int block_scan_incl(int v) {
    __shared__ int ws[32];
    int lane = threadIdx.x & 31;
    int w = threadIdx.x >> 5;
#pragma unroll
    for (int o = 1; o < 32; o <<= 1) {
        int n = __shfl_up_sync(0xffffffffu, v, o);
        if (lane >= o) v += n;
    }
    if (lane == 31) ws[w] = v;
    __syncthreads();
    if (w == 0) {
        int s = ws[lane];
#pragma unroll
        for (int o = 1; o < 32; o <<= 1) {
            int n = __shfl_up_sync(0xffffffffu, s, o);
            if (lane >= o) s += n;
        }
        ws[lane] = s;
    }
    __syncthreads();
    if (w > 0) v += ws[w - 1];
    return v;
}

__global__ void k_scan_a() {  // 1024 threads/block
    int i = blockIdx.x * 1024 + threadIdx.x;
    int c = (i < NN) ? g_cnt[i] : 0;
    int s = block_scan_incl(c);
    if (i < NN) g_rowptr[i + 1] = s;
    if (threadIdx.x == 1023) g_bsum[blockIdx.x] = s;
}

__global__ void k_scan_b(int nblk) {  // 1 block, 1024 threads
    int v = (threadIdx.x < nblk) ? g_bsum[threadIdx.x] : 0;
    int s = block_scan_incl(v);
    if (threadIdx.x < nblk) g_boff[threadIdx.x] = s - v;  // exclusive
}

__global__ void k_scan_c() {  // also produces g_fill (fused fill_init)
    int i = blockIdx.x * 1024 + threadIdx.x;
    if (i < NN) {
        int v = g_rowptr[i + 1] + g_boff[blockIdx.x];
        g_rowptr[i + 1] = v;
        if (i + 1 < NN) g_fill[i + 1] = v;
        if (i == 0) { g_rowptr[0] = 0; g_fill[0] = 0; }
    }
}

__global__ void k_scatter(const int* __restrict__ u) {
    int i = blockIdx.x * blockDim.x + threadIdx.x;
    if (i >= EE) return;
    int s, d;
    if (g_is64) { s = u[2 * i]; d = u[2 * EE + 2 * i]; }
    else        { s = u[i];     d = u[EE + i]; }
    int p = atomicAdd(&g_fill[d], 1);
    g_colidx[p] = s;
}

// ---------------- GEMM: Y[n][j] = dinv[n] * sum_k H[n][k] W[k][j] ----------------
template <int FIN, int FOUT>
__global__ void __launch_bounds__(128) k_gemm(const float* __restrict__ H,
                                              const float* __restrict__ W,
                                              float* __restrict__ Y) {
    constexpr int BN = 64, KB = 32, TN = FOUT / 16, TM = 8;
    __shared__ float Ws[FIN * FOUT];
    __shared__ float Xs[KB][BN + 4];
    int tid = threadIdx.x;
    for (int i = tid; i < FIN * FOUT; i += 128) Ws[i] = W[i];
    int nb = blockIdx.x * BN;
    float acc[TM][TN];
#pragma unroll
    for (int i = 0; i < TM; i++)
#pragma unroll
        for (int j = 0; j < TN; j++) acc[i][j] = 0.f;
    int tx = tid & 15, ty = tid >> 4;
    int n0 = ty * TM, j0 = tx * TN;
    for (int kb = 0; kb < FIN; kb += KB) {
        __syncthreads();
        for (int idx = tid; idx < KB * BN; idx += 128) {
            int n = idx >> 5, k = idx & 31;
            int gn = nb + n;
            Xs[k][n] = (gn < NN) ? H[(size_t)gn * FIN + kb + k] : 0.f;
        }
        __syncthreads();
#pragma unroll
        for (int k = 0; k < KB; k++) {
            float xv[TM];
            float4 xa = *(const float4*)&Xs[k][n0];
            float4 xb = *(const float4*)&Xs[k][n0 + 4];
            xv[0] = xa.x; xv[1] = xa.y; xv[2] = xa.z; xv[3] = xa.w;
            xv[4] = xb.x; xv[5] = xb.y; xv[6] = xb.z; xv[7] = xb.w;
            float wv[TN];
            const float* wr = &Ws[(kb + k) * FOUT + j0];
#pragma unroll
            for (int j = 0; j < TN; j += 4) {
                float4 w4 = *(const float4*)&wr[j];
                wv[j] = w4.x; wv[j + 1] = w4.y; wv[j + 2] = w4.z; wv[j + 3] = w4.w;
            }
#pragma unroll
            for (int i = 0; i < TM; i++)
#pragma unroll
                for (int j = 0; j < TN; j++) acc[i][j] = fmaf(xv[i], wv[j], acc[i][j]);
        }
    }
#pragma unroll
    for (int i = 0; i < TM; i++) {
        int gn = nb + n0 + i;
        if (gn < NN) {
            float dv = g_dinv[gn];
            float* yr = Y + (size_t)gn * FOUT + j0;
#pragma unroll
            for (int j = 0; j < TN; j += 4) {
                float4 o;
                o.x = acc[i][j] * dv; o.y = acc[i][j + 1] * dv;
                o.z = acc[i][j + 2] * dv; o.w = acc[i][j + 3] * dv;
                *(float4*)&yr[j] = o;
            }
        }
    }
}

// ---------------- aggregation + bias + LayerNorm + ELU (warp per node) ----------------
template <int F>
__global__ void __launch_bounds__(256) k_agg(const float* __restrict__ Y,
                                             const float* __restrict__ bias,
                                             const float* __restrict__ gam,
                                             const float* __restrict__ bet,
                                             float* __restrict__ O) {
    constexpr int VPL = F / 32;
    int wid = threadIdx.x >> 5;
    int lane = threadIdx.x & 31;
    int node = blockIdx.x * 8 + wid;
    if (node >= NN) return;
    int fi = lane * VPL;
    const float* yself = Y + (size_t)node * F + fi;
    float acc[VPL];
    if constexpr (VPL == 2) {
        float2 t = *(const float2*)yself; acc[0] = t.x; acc[1] = t.y;
    } else {
        float4 t = *(const float4*)yself;
        acc[0] = t.x; acc[1] = t.y; acc[2] = t.z; acc[3] = t.w;
    }
    int e = g_rowptr[node];
    int end = g_rowptr[node + 1];
    for (; e + 4 <= end; e += 4) {
        int s0 = __ldg(&g_colidx[e]);
        int s1 = __ldg(&g_colidx[e + 1]);
        int s2 = __ldg(&g_colidx[e + 2]);
        int s3 = __ldg(&g_colidx[e + 3]);
        const float* r0 = Y + (size_t)s0 * F + fi;
        const float* r1 = Y + (size_t)s1 * F + fi;
        const float* r2 = Y + (size_t)s2 * F + fi;
        const float* r3 = Y + (size_t)s3 * F + fi;
        if constexpr (VPL == 2) {
            float2 a = *(const float2*)r0, b = *(const float2*)r1;
            float2 c = *(const float2*)r2, d = *(const float2*)r3;
            acc[0] += (a.x + b.x) + (c.x + d.x);
            acc[1] += (a.y + b.y) + (c.y + d.y);
        } else {
            float4 a = *(const float4*)r0, b = *(const float4*)r1;
            float4 c = *(const float4*)r2, d = *(const float4*)r3;
            acc[0] += (a.x + b.x) + (c.x + d.x);
            acc[1] += (a.y + b.y) + (c.y + d.y);
            acc[2] += (a.z + b.z) + (c.z + d.z);
            acc[3] += (a.w + b.w) + (c.w + d.w);
        }
    }
    for (; e < end; e++) {
        int s0 = __ldg(&g_colidx[e]);
        const float* r0 = Y + (size_t)s0 * F + fi;
        if constexpr (VPL == 2) {
            float2 a = *(const float2*)r0; acc[0] += a.x; acc[1] += a.y;
        } else {
            float4 a = *(const float4*)r0;
            acc[0] += a.x; acc[1] += a.y; acc[2] += a.z; acc[3] += a.w;
        }
    }
    float dv = g_dinv[node];
    float t[VPL];
    float s1 = 0.f;
#pragma unroll
    for (int v = 0; v < VPL; v++) { t[v] = acc[v] * dv + bias[fi + v]; s1 += t[v]; }
#pragma unroll
    for (int o = 16; o > 0; o >>= 1) s1 += __shfl_xor_sync(0xffffffffu, s1, o);
    float mu = s1 * (1.0f / F);
    float s2 = 0.f;
#pragma unroll
    for (int v = 0; v < VPL; v++) { float d = t[v] - mu; s2 += d * d; }
#pragma unroll
    for (int o = 16; o > 0; o >>= 1) s2 += __shfl_xor_sync(0xffffffffu, s2, o);
    float rs = rsqrtf(s2 * (1.0f / F) + 1e-5f);
    float ov[VPL];
#pragma unroll
    for (int v = 0; v < VPL; v++) {
        float z = (t[v] - mu) * rs * gam[fi + v] + bet[fi + v];
        ov[v] = (z > 0.f) ? z : expm1f(z);
    }
    float* orow = O + (size_t)node * F + fi;
    if constexpr (VPL == 2) {
        *(float2*)orow = make_float2(ov[0], ov[1]);
    } else {
        *(float4*)orow = make_float4(ov[0], ov[1], ov[2], ov[3]);
    }
}

// ---------------- head: (h@lw1+lb1) -> LN -> ELU -> @lw2+lb2 ----------------
__global__ void __launch_bounds__(256) k_head(const float* __restrict__ H,
                                              const float* __restrict__ lw1,
                                              const float* __restrict__ lb1,
                                              const float* __restrict__ g4,
                                              const float* __restrict__ be4,
                                              const float* __restrict__ lw2,
                                              const float* __restrict__ lb2,
                                              float* __restrict__ out) {
    __shared__ float W1s[64 * 32];
    __shared__ float W2s[32 * 32];
    __shared__ float hs[8][64];
    int tid = threadIdx.x;
    for (int i = tid; i < 64 * 32; i += 256) W1s[i] = lw1[i];
    for (int i = tid; i < 32 * 32; i += 256) W2s[i] = lw2[i];
    int wid = tid >> 5, lane = tid & 31;
    int node = blockIdx.x * 8 + wid;
    __syncthreads();
    if (node >= NN) return;
    const float* hr = H + (size_t)node * 64;
    hs[wid][lane] = hr[lane];
    hs[wid][lane + 32] = hr[lane + 32];
    __syncwarp();
    float u = lb1[lane];
#pragma unroll
    for (int k = 0; k < 64; k++) u = fmaf(hs[wid][k], W1s[k * 32 + lane], u);
    float s = u;
#pragma unroll
    for (int o = 16; o > 0; o >>= 1) s += __shfl_xor_sync(0xffffffffu, s, o);
    float mu = s * (1.0f / 32.0f);
    float d = u - mu;
    float s2 = d * d;
#pragma unroll
    for (int o = 16; o > 0; o >>= 1) s2 += __shfl_xor_sync(0xffffffffu, s2, o);
    float rs = rsqrtf(s2 * (1.0f / 32.0f) + 1e-5f);
    float v = d * rs * g4[lane] + be4[lane];
    v = (v > 0.f) ? v : expm1f(v);
    float o2 = lb2[lane];
#pragma unroll
    for (int k = 0; k < 32; k++) {
        float vk = __shfl_sync(0xffffffffu, v, k);
        o2 = fmaf(vk, W2s[k * 32 + lane], o2);
    }
    out[(size_t)node * 32 + lane] = o2;
}

// ---------------- launch ----------------
extern "C" void kernel_launch(void* const* d_in, const int* in_sizes, int n_in,
                              void* d_out, int out_size) {
    const float* x   = (const float*)d_in[0];
    const int*   ei  = (const int*)d_in[1];
    const float* W1  = (const float*)d_in[2];
    const float* b1  = (const float*)d_in[3];
    const float* g1  = (const float*)d_in[4];
    const float* be1 = (const float*)d_in[5];
    const float* W2  = (const float*)d_in[6];
    const float* b2  = (const float*)d_in[7];
    const float* g2  = (const float*)d_in[8];
    const float* be2 = (const float*)d_in[9];
    const float* W3  = (const float*)d_in[10];
    const float* b3  = (const float*)d_in[11];
    const float* g3  = (const float*)d_in[12];
    const float* be3 = (const float*)d_in[13];
    const float* lw1 = (const float*)d_in[14];
    const float* lb1 = (const float*)d_in[15];
    const float* g4  = (const float*)d_in[16];
    const float* be4 = (const float*)d_in[17];
    const float* lw2 = (const float*)d_in[18];
    const float* lb2 = (const float*)d_in[19];
    float* out = (float*)d_out;

    void *py, *pA, *pB, *pc;
    cudaGetSymbolAddress(&py, g_y);
    cudaGetSymbolAddress(&pA, g_hA);
    cudaGetSymbolAddress(&pB, g_hB);
    cudaGetSymbolAddress(&pc, g_cnt);
    float* Y  = (float*)py;
    float* hA = (float*)pA;
    float* hB = (float*)pB;

    const int EB  = (EE + 255) / 256;
    const int NBl = (NN + 255) / 256;
    const int NSC = (NN + 1023) / 1024;  // 98
    const int GB  = (NN + 63) / 64;
    const int AB  = (NN + 7) / 8;

    // CSR prefix needed by GEMM1 (dinv only)
    cudaMemsetAsync(pc, 0, NN * sizeof(int), 0);
    k_detect<<<1, 256>>>(ei);
    k_hist<<<EB, 256>>>(ei);
    k_dinv<<<NBl, 256>>>();

    // Fork: GEMM1 on s2 overlaps scan+scatter on main stream.
    cudaStream_t s2;
    cudaEvent_t evA, evB;
    cudaStreamCreateWithFlags(&s2, cudaStreamNonBlocking);
    cudaEventCreateWithFlags(&evA, cudaEventDisableTiming);
    cudaEventCreateWithFlags(&evB, cudaEventDisableTiming);

    cudaEventRecord(evA, 0);
    cudaStreamWaitEvent(s2, evA, 0);
    k_gemm<128, 64><<<GB, 128, 0, s2>>>(x, W1, Y);
    cudaEventRecord(evB, s2);

    k_scan_a<<<NSC, 1024>>>();
    k_scan_b<<<1, 1024>>>(NSC);
    k_scan_c<<<NSC, 1024>>>();
    k_scatter<<<EB, 256>>>(ei);

    cudaStreamWaitEvent(0, evB, 0);  // join GEMM1

    k_agg<64><<<AB, 256>>>(Y, b1, g1, be1, hA);
    k_gemm<64, 128><<<GB, 128>>>(hA, W2, Y);
    k_agg<128><<<AB, 256>>>(Y, b2, g2, be2, hB);
    k_gemm<128, 64><<<GB, 128>>>(hB, W3, Y);
    k_agg<64><<<AB, 256>>>(Y, b3, g3, be3, hA);
    k_head<<<AB, 256>>>(hA, lw1, lb1, g4, be4, lw2, lb2, out);
}

// round 16
// speedup vs baseline: 1.4564x; 1.0221x over previous
#include <cuda_runtime.h>
#include <math.h>

#define NN 100000
#define EE 1600000

// ---------------- scratch (static device globals; no allocation) ----------------
__device__ int   g_is64;
__device__ int   g_cnt[NN];
__device__ int   g_rowptr[NN + 1];
__device__ int   g_fill[NN];
__device__ int   g_colidx[EE];
__device__ int   g_bsum[128];
__device__ int   g_boff[128];
__device__ float g_dinv[NN];
__device__ float g_y[(size_t)NN * 128];
__device__ float g_hA[(size_t)NN * 128];
__device__ float g_hB[(size_t)NN * 128];

// ---------------- edge-index format detection ----------------
// int64 little-endian with values < 2^31 -> all odd 32-bit words of the first
// 256 pairs are zero; int32 data makes them random node ids.
__global__ void k_detect(const int* __restrict__ u) {
    __shared__ int any;
    if (threadIdx.x == 0) any = 0;
    __syncthreads();
    if (u[2 * threadIdx.x + 1] != 0) atomicOr(&any, 1);
    __syncthreads();
    if (threadIdx.x == 0) g_is64 = any ? 0 : 1;
}

// ---------------- degree / CSR build (direct edge reads) ----------------
__global__ void k_hist(const int* __restrict__ u) {
    int i = blockIdx.x * blockDim.x + threadIdx.x;
    if (i >= EE) return;
    int d = g_is64 ? u[2 * EE + 2 * i] : u[EE + i];
    atomicAdd(&g_cnt[d], 1);
}

__global__ void k_dinv() {
    int i = blockIdx.x * blockDim.x + threadIdx.x;
    if (i < NN) g_dinv[i] = rsqrtf((float)g_cnt[i] + 1.0f);
}

__device__ __forceinline__ int block_scan_incl(int v) {
    __shared__ int ws[32];
    int lane = threadIdx.x & 31;
    int w = threadIdx.x >> 5;
#pragma unroll
    for (int o = 1; o < 32; o <<= 1) {
        int n = __shfl_up_sync(0xffffffffu, v, o);
        if (lane >= o) v += n;
    }
    if (lane == 31) ws[w] = v;
    __syncthreads();
    if (w == 0) {
        int s = ws[lane];
#pragma unroll
        for (int o = 1; o < 32; o <<= 1) {
            int n = __shfl_up_sync(0xffffffffu, s, o);
            if (lane >= o) s += n;
        }
        ws[lane] = s;
    }
    __syncthreads();
    if (w > 0) v += ws[w - 1];
    return v;
}

__global__ void k_scan_a() {  // 1024 threads/block
    int i = blockIdx.x * 1024 + threadIdx.x;
    int c = (i < NN) ? g_cnt[i] : 0;
    int s = block_scan_incl(c);
    if (i < NN) g_rowptr[i + 1] = s;
    if (threadIdx.x == 1023) g_bsum[blockIdx.x] = s;
}

__global__ void k_scan_b(int nblk) {  // 1 block, 1024 threads
    int v = (threadIdx.x < nblk) ? g_bsum[threadIdx.x] : 0;
    int s = block_scan_incl(v);
    if (threadIdx.x < nblk) g_boff[threadIdx.x] = s - v;  // exclusive
}

__global__ void k_scan_c() {  // also produces g_fill (fused fill_init)
    int i = blockIdx.x * 1024 + threadIdx.x;
    if (i < NN) {
        int v = g_rowptr[i + 1] + g_boff[blockIdx.x];
        g_rowptr[i + 1] = v;
        if (i + 1 < NN) g_fill[i + 1] = v;
        if (i == 0) { g_rowptr[0] = 0; g_fill[0] = 0; }
    }
}

__global__ void k_scatter(const int* __restrict__ u) {
    int i = blockIdx.x * blockDim.x + threadIdx.x;
    if (i >= EE) return;
    int s, d;
    if (g_is64) { s = u[2 * i]; d = u[2 * EE + 2 * i]; }
    else        { s = u[i];     d = u[EE + i]; }
    int p = atomicAdd(&g_fill[d], 1);
    g_colidx[p] = s;
}

// ---------------- GEMM: Y[n][j] = dinv[n] * sum_k H[n][k] W[k][j] ----------------
// W streamed through smem in KB-row chunks to cut smem 41KB -> ~17/25KB and
// lift occupancy (27.6% -> ~37%).
template <int FIN, int FOUT>
__global__ void __launch_bounds__(128) k_gemm(const float* __restrict__ H,
                                              const float* __restrict__ W,
                                              float* __restrict__ Y) {
    constexpr int BN = 64, KB = 32, TN = FOUT / 16, TM = 8;
    __shared__ float Ws[KB][FOUT];
    __shared__ float Xs[KB][BN + 4];
    int tid = threadIdx.x;
    int nb = blockIdx.x * BN;
    float acc[TM][TN];
#pragma unroll
    for (int i = 0; i < TM; i++)
#pragma unroll
        for (int j = 0; j < TN; j++) acc[i][j] = 0.f;
    int tx = tid & 15, ty = tid >> 4;
    int n0 = ty * TM, j0 = tx * TN;
    for (int kb = 0; kb < FIN; kb += KB) {
        __syncthreads();
        // stage W chunk: KB x FOUT
        for (int idx = tid; idx < KB * FOUT; idx += 128) {
            int k = idx / FOUT, j = idx % FOUT;
            Ws[k][j] = W[(kb + k) * FOUT + j];
        }
        // stage X chunk: KB x BN
        for (int idx = tid; idx < KB * BN; idx += 128) {
            int n = idx >> 5, k = idx & 31;
            int gn = nb + n;
            Xs[k][n] = (gn < NN) ? H[(size_t)gn * FIN + kb + k] : 0.f;
        }
        __syncthreads();
#pragma unroll
        for (int k = 0; k < KB; k++) {
            float xv[TM];
            float4 xa = *(const float4*)&Xs[k][n0];
            float4 xb = *(const float4*)&Xs[k][n0 + 4];
            xv[0] = xa.x; xv[1] = xa.y; xv[2] = xa.z; xv[3] = xa.w;
            xv[4] = xb.x; xv[5] = xb.y; xv[6] = xb.z; xv[7] = xb.w;
            float wv[TN];
            const float* wr = &Ws[k][j0];
#pragma unroll
            for (int j = 0; j < TN; j += 4) {
                float4 w4 = *(const float4*)&wr[j];
                wv[j] = w4.x; wv[j + 1] = w4.y; wv[j + 2] = w4.z; wv[j + 3] = w4.w;
            }
#pragma unroll
            for (int i = 0; i < TM; i++)
#pragma unroll
                for (int j = 0; j < TN; j++) acc[i][j] = fmaf(xv[i], wv[j], acc[i][j]);
        }
    }
#pragma unroll
    for (int i = 0; i < TM; i++) {
        int gn = nb + n0 + i;
        if (gn < NN) {
            float dv = g_dinv[gn];
            float* yr = Y + (size_t)gn * FOUT + j0;
#pragma unroll
            for (int j = 0; j < TN; j += 4) {
                float4 o;
                o.x = acc[i][j] * dv; o.y = acc[i][j + 1] * dv;
                o.z = acc[i][j + 2] * dv; o.w = acc[i][j + 3] * dv;
                *(float4*)&yr[j] = o;
            }
        }
    }
}

// ---------------- aggregation + bias + LayerNorm + ELU (warp per node) ----------------
template <int F>
__global__ void __launch_bounds__(256) k_agg(const float* __restrict__ Y,
                                             const float* __restrict__ bias,
                                             const float* __restrict__ gam,
                                             const float* __restrict__ bet,
                                             float* __restrict__ O) {
    constexpr int VPL = F / 32;
    int wid = threadIdx.x >> 5;
    int lane = threadIdx.x & 31;
    int node = blockIdx.x * 8 + wid;
    if (node >= NN) return;
    int fi = lane * VPL;
    const float* yself = Y + (size_t)node * F + fi;
    float acc[VPL];
    if constexpr (VPL == 2) {
        float2 t = *(const float2*)yself; acc[0] = t.x; acc[1] = t.y;
    } else {
        float4 t = *(const float4*)yself;
        acc[0] = t.x; acc[1] = t.y; acc[2] = t.z; acc[3] = t.w;
    }
    int e = g_rowptr[node];
    int end = g_rowptr[node + 1];
    for (; e + 4 <= end; e += 4) {
        int s0 = __ldg(&g_colidx[e]);
        int s1 = __ldg(&g_colidx[e + 1]);
        int s2 = __ldg(&g_colidx[e + 2]);
        int s3 = __ldg(&g_colidx[e + 3]);
        const float* r0 = Y + (size_t)s0 * F + fi;
        const float* r1 = Y + (size_t)s1 * F + fi;
        const float* r2 = Y + (size_t)s2 * F + fi;
        const float* r3 = Y + (size_t)s3 * F + fi;
        if constexpr (VPL == 2) {
            float2 a = *(const float2*)r0, b = *(const float2*)r1;
            float2 c = *(const float2*)r2, d = *(const float2*)r3;
            acc[0] += (a.x + b.x) + (c.x + d.x);
            acc[1] += (a.y + b.y) + (c.y + d.y);
        } else {
            float4 a = *(const float4*)r0, b = *(const float4*)r1;
            float4 c = *(const float4*)r2, d = *(const float4*)r3;
            acc[0] += (a.x + b.x) + (c.x + d.x);
            acc[1] += (a.y + b.y) + (c.y + d.y);
            acc[2] += (a.z + b.z) + (c.z + d.z);
            acc[3] += (a.w + b.w) + (c.w + d.w);
        }
    }
    for (; e < end; e++) {
        int s0 = __ldg(&g_colidx[e]);
        const float* r0 = Y + (size_t)s0 * F + fi;
        if constexpr (VPL == 2) {
            float2 a = *(const float2*)r0; acc[0] += a.x; acc[1] += a.y;
        } else {
            float4 a = *(const float4*)r0;
            acc[0] += a.x; acc[1] += a.y; acc[2] += a.z; acc[3] += a.w;
        }
    }
    float dv = g_dinv[node];
    float t[VPL];
    float s1 = 0.f;
#pragma unroll
    for (int v = 0; v < VPL; v++) { t[v] = acc[v] * dv + bias[fi + v]; s1 += t[v]; }
#pragma unroll
    for (int o = 16; o > 0; o >>= 1) s1 += __shfl_xor_sync(0xffffffffu, s1, o);
    float mu = s1 * (1.0f / F);
    float s2 = 0.f;
#pragma unroll
    for (int v = 0; v < VPL; v++) { float d = t[v] - mu; s2 += d * d; }
#pragma unroll
    for (int o = 16; o > 0; o >>= 1) s2 += __shfl_xor_sync(0xffffffffu, s2, o);
    float rs = rsqrtf(s2 * (1.0f / F) + 1e-5f);
    float ov[VPL];
#pragma unroll
    for (int v = 0; v < VPL; v++) {
        float z = (t[v] - mu) * rs * gam[fi + v] + bet[fi + v];
        ov[v] = (z > 0.f) ? z : expm1f(z);
    }
    float* orow = O + (size_t)node * F + fi;
    if constexpr (VPL == 2) {
        *(float2*)orow = make_float2(ov[0], ov[1]);
    } else {
        *(float4*)orow = make_float4(ov[0], ov[1], ov[2], ov[3]);
    }
}

// ---------------- head: (h@lw1+lb1) -> LN -> ELU -> @lw2+lb2 ----------------
__global__ void __launch_bounds__(256) k_head(const float* __restrict__ H,
                                              const float* __restrict__ lw1,
                                              const float* __restrict__ lb1,
                                              const float* __restrict__ g4,
                                              const float* __restrict__ be4,
                                              const float* __restrict__ lw2,
                                              const float* __restrict__ lb2,
                                              float* __restrict__ out) {
    __shared__ float W1s[64 * 32];
    __shared__ float W2s[32 * 32];
    __shared__ float hs[8][64];
    int tid = threadIdx.x;
    for (int i = tid; i < 64 * 32; i += 256) W1s[i] = lw1[i];
    for (int i = tid; i < 32 * 32; i += 256) W2s[i] = lw2[i];
    int wid = tid >> 5, lane = tid & 31;
    int node = blockIdx.x * 8 + wid;
    __syncthreads();
    if (node >= NN) return;
    const float* hr = H + (size_t)node * 64;
    hs[wid][lane] = hr[lane];
    hs[wid][lane + 32] = hr[lane + 32];
    __syncwarp();
    float u = lb1[lane];
#pragma unroll
    for (int k = 0; k < 64; k++) u = fmaf(hs[wid][k], W1s[k * 32 + lane], u);
    float s = u;
#pragma unroll
    for (int o = 16; o > 0; o >>= 1) s += __shfl_xor_sync(0xffffffffu, s, o);
    float mu = s * (1.0f / 32.0f);
    float d = u - mu;
    float s2 = d * d;
#pragma unroll
    for (int o = 16; o > 0; o >>= 1) s2 += __shfl_xor_sync(0xffffffffu, s2, o);
    float rs = rsqrtf(s2 * (1.0f / 32.0f) + 1e-5f);
    float v = d * rs * g4[lane] + be4[lane];
    v = (v > 0.f) ? v : expm1f(v);
    float o2 = lb2[lane];
#pragma unroll
    for (int k = 0; k < 32; k++) {
        float vk = __shfl_sync(0xffffffffu, v, k);
        o2 = fmaf(vk, W2s[k * 32 + lane], o2);
    }
    out[(size_t)node * 32 + lane] = o2;
}

// ---------------- launch ----------------
extern "C" void kernel_launch(void* const* d_in, const int* in_sizes, int n_in,
                              void* d_out, int out_size) {
    const float* x   = (const float*)d_in[0];
    const int*   ei  = (const int*)d_in[1];
    const float* W1  = (const float*)d_in[2];
    const float* b1  = (const float*)d_in[3];
    const float* g1  = (const float*)d_in[4];
    const float* be1 = (const float*)d_in[5];
    const float* W2  = (const float*)d_in[6];
    const float* b2  = (const float*)d_in[7];
    const float* g2  = (const float*)d_in[8];
    const float* be2 = (const float*)d_in[9];
    const float* W3  = (const float*)d_in[10];
    const float* b3  = (const float*)d_in[11];
    const float* g3  = (const float*)d_in[12];
    const float* be3 = (const float*)d_in[13];
    const float* lw1 = (const float*)d_in[14];
    const float* lb1 = (const float*)d_in[15];
    const float* g4  = (const float*)d_in[16];
    const float* be4 = (const float*)d_in[17];
    const float* lw2 = (const float*)d_in[18];
    const float* lb2 = (const float*)d_in[19];
    float* out = (float*)d_out;

    void *py, *pA, *pB, *pc;
    cudaGetSymbolAddress(&py, g_y);
    cudaGetSymbolAddress(&pA, g_hA);
    cudaGetSymbolAddress(&pB, g_hB);
    cudaGetSymbolAddress(&pc, g_cnt);
    float* Y  = (float*)py;
    float* hA = (float*)pA;
    float* hB = (float*)pB;

    const int EB  = (EE + 255) / 256;
    const int NBl = (NN + 255) / 256;
    const int NSC = (NN + 1023) / 1024;  // 98
    const int GB  = (NN + 63) / 64;
    const int AB  = (NN + 7) / 8;

    // CSR prefix needed by GEMM1 (dinv only)
    cudaMemsetAsync(pc, 0, NN * sizeof(int), 0);
    k_detect<<<1, 256>>>(ei);
    k_hist<<<EB, 256>>>(ei);
    k_dinv<<<NBl, 256>>>();

    // Fork: GEMM1 on s2 overlaps scan+scatter on main stream.
    cudaStream_t s2;
    cudaEvent_t evA, evB;
    cudaStreamCreateWithFlags(&s2, cudaStreamNonBlocking);
    cudaEventCreateWithFlags(&evA, cudaEventDisableTiming);
    cudaEventCreateWithFlags(&evB, cudaEventDisableTiming);

    cudaEventRecord(evA, 0);
    cudaStreamWaitEvent(s2, evA, 0);
    k_gemm<128, 64><<<GB, 128, 0, s2>>>(x, W1, Y);
    cudaEventRecord(evB, s2);

    k_scan_a<<<NSC, 1024>>>();
    k_scan_b<<<1, 1024>>>(NSC);
    k_scan_c<<<NSC, 1024>>>();
    k_scatter<<<EB, 256>>>(ei);

    cudaStreamWaitEvent(0, evB, 0);  // join GEMM1

    k_agg<64><<<AB, 256>>>(Y, b1, g1, be1, hA);
    k_gemm<64, 128><<<GB, 128>>>(hA, W2, Y);
    k_agg<128><<<AB, 256>>>(Y, b2, g2, be2, hB);
    k_gemm<128, 64><<<GB, 128>>>(hB, W3, Y);
    k_agg<64><<<AB, 256>>>(Y, b3, g3, be3, hA);
    k_head<<<AB, 256>>>(hA, lw1, lb1, g4, be4, lw2, lb2, out);
}